// round 14
// baseline (speedup 1.0000x reference)
#include <cuda_runtime.h>
#include <cuda_bf16.h>
#include <cstdint>

#define NB 2
#define NT 2048
#define NV 32000
#define NE 512
#define NH 1024
#define NM 128
#define NROW (NB*NT)      // 4096
#define GRU_CTAS 128

// ---------------- scratch (module-static device memory; no cudaMalloc) -------
__device__ __align__(16) float g_xproj[(size_t)NROW*3*NH];
__device__ __align__(16) float g_states[(size_t)NROW*NH];
__device__ __align__(16) float g_head[(size_t)NROW*4*NE];
__device__ __align__(16) float g_bfeat[NROW*NE];
__device__ __align__(16) float g_qk[(size_t)NROW*2*NM];
__device__ __align__(16) float g_bqk[2*NM];
__device__ __align__(16) float g_gate[NROW];
__device__ __align__(16) float g_h[2][NB*NH];      // double-buffered GRU state
__device__ int g_cnt[NT];                          // per-step barrier counters

// bf16 triple-expanded operands (K' = 3K)
__device__ __align__(16) __nv_bfloat16 x_e3  [(size_t)NROW*3*NE];
__device__ __align__(16) __nv_bfloat16 x_wih3[(size_t)3*NH*3*NE];
__device__ __align__(16) __nv_bfloat16 x_s3  [(size_t)NROW*3*NH];
__device__ __align__(16) __nv_bfloat16 x_wfc3[(size_t)4*NE*3*NH];
__device__ __align__(16) __nv_bfloat16 x_hd3 [(size_t)NROW*3*4*NE];
__device__ __align__(16) __nv_bfloat16 x_wp3 [(size_t)NE*3*4*NE];
__device__ __align__(16) __nv_bfloat16 x_f3  [(size_t)NROW*3*NE];
__device__ __align__(16) __nv_bfloat16 x_t3  [(size_t)NV*3*NE];
__device__ __align__(16) __nv_bfloat16 x_wqk3[(size_t)2*NM*3*NH];

// ---------------- operand expansion: fp32 -> triple bf16 ---------------------
__global__ void __launch_bounds__(256) expand3_kernel(
    const float* __restrict__ src, __nv_bfloat16* __restrict__ dst, int n8, int bmode)
{
    int i = blockIdx.x*256 + threadIdx.x;
    if (i >= n8) return;
    const float4* s4 = (const float4*)src + (size_t)i*2;
    float4 v0 = s4[0], v1 = s4[1];
    float a[8] = {v0.x, v0.y, v0.z, v0.w, v1.x, v1.y, v1.z, v1.w};
    __align__(16) __nv_bfloat16 o[24];
    #pragma unroll
    for (int j = 0; j < 8; j++) {
        float x = a[j];
        __nv_bfloat16 h = __float2bfloat16(x);
        __nv_bfloat16 l = __float2bfloat16(x - __bfloat162float(h));
        if (bmode) { o[3*j] = h; o[3*j+1] = l; o[3*j+2] = h; }
        else       { o[3*j] = h; o[3*j+1] = h; o[3*j+2] = l; }
    }
    uint4* d4 = (uint4*)(dst + (size_t)i*24);
    const uint4* ov = (const uint4*)o;
    d4[0] = ov[0]; d4[1] = ov[1]; d4[2] = ov[2];
}

// ================= HMMA (mma.sync) bf16 GEMM + 3-stage cp.async =============
__device__ __forceinline__ uint32_t smem_u32(const void* p) {
    uint32_t a;
    asm("{ .reg .u64 t; cvta.to.shared.u64 t, %1; cvt.u32.u64 %0, t; }" : "=r"(a) : "l"(p));
    return a;
}

__device__ __forceinline__ int swoff(int row, int ch) {
    int p = row >> 1;
    return (p << 7) + (((((row & 1) << 2) | ch) ^ (p & 7)) << 4);
}

#define CPA16(dst, src) \
    asm volatile("cp.async.cg.shared.global [%0], [%1], 16;" :: "r"(dst), "l"(src) : "memory")
#define CPA_COMMIT() asm volatile("cp.async.commit_group;" ::: "memory")
#define CPA_WAIT0()  asm volatile("cp.async.wait_group 0;"  ::: "memory")
#define CPA_WAIT1()  asm volatile("cp.async.wait_group 1;"  ::: "memory")

#define LDMX4(r0,r1,r2,r3, addr) \
    asm volatile("ldmatrix.sync.aligned.m8n8.x4.shared.b16 {%0,%1,%2,%3}, [%4];" \
        : "=r"(r0),"=r"(r1),"=r"(r2),"=r"(r3) : "r"(addr))

#define MMA16816(d, a, b0v, b1v) \
    asm volatile("mma.sync.aligned.m16n8k16.row.col.f32.bf16.bf16.f32 " \
        "{%0,%1,%2,%3}, {%4,%5,%6,%7}, {%8,%9}, {%0,%1,%2,%3};" \
        : "+f"((d)[0]),"+f"((d)[1]),"+f"((d)[2]),"+f"((d)[3]) \
        : "r"((a)[0]),"r"((a)[1]),"r"((a)[2]),"r"((a)[3]), "r"(b0v),"r"(b1v))

#define GEMM_SMEM (49152 + 1024)

__global__ void __launch_bounds__(256) hmma_gemm(
    const __nv_bfloat16* __restrict__ A, const __nv_bfloat16* __restrict__ B,
    const float* __restrict__ bias, float* __restrict__ C,
    int M, int N, int K3, int act)
{
    extern __shared__ char dsm_raw[];
    const uint32_t draw  = smem_u32(dsm_raw);
    const uint32_t dbase = (draw + 1023) & ~1023u;

    const int tid  = threadIdx.x;
    const int lane = tid & 31, wid = tid >> 5;

    // CTA rasterization swizzle: GM=8 M-tiles per launch-order group.
    const int nbn = gridDim.x;
    const int bid = blockIdx.y * nbn + blockIdx.x;
    const int grp = bid / (nbn << 3);
    const int rem = bid - grp * (nbn << 3);
    const int bm  = ((grp << 3) + (rem & 7)) << 7;
    const int bn  = (rem >> 3) << 7;

    const int wm = (wid >> 2) << 6;
    const int wn = (wid & 3) << 5;

    const int row0 = tid >> 2,         ch0 = tid & 3;
    const int row1 = (tid + 256) >> 2, ch1 = tid & 3;
    const int so0 = swoff(row0, ch0), so1 = swoff(row1, ch1);
    const __nv_bfloat16* Ag0 = A + (size_t)(bm + row0)*K3 + ch0*8;
    const __nv_bfloat16* Ag1 = A + (size_t)(bm + row1)*K3 + ch1*8;
    const __nv_bfloat16* Bg0 = B + (size_t)(bn + row0)*K3 + ch0*8;
    const __nv_bfloat16* Bg1 = B + (size_t)(bn + row1)*K3 + ch1*8;

    const int g = lane >> 3, rr = lane & 7;
    const int lrow_a = wm + ((g & 1) << 3) + rr;
    const int lrow_b = wn + ((g & 1) << 3) + rr;
    const int kc = g >> 1;

    float acc[4][4][4];
    #pragma unroll
    for (int i = 0; i < 4; i++)
        #pragma unroll
        for (int j = 0; j < 4; j++)
            #pragma unroll
            for (int r = 0; r < 4; r++) acc[i][j][r] = 0.f;

    const int nk = K3 >> 5;
    {
        const uint32_t sA = dbase, sB = dbase + 8192;
        CPA16(sA + so0, Ag0); CPA16(sA + so1, Ag1);
        CPA16(sB + so0, Bg0); CPA16(sB + so1, Bg1);
        CPA_COMMIT();
    }
    if (nk > 1) {
        const uint32_t sA = dbase + 16384, sB = dbase + 16384 + 8192;
        CPA16(sA + so0, Ag0 + 32); CPA16(sA + so1, Ag1 + 32);
        CPA16(sB + so0, Bg0 + 32); CPA16(sB + so1, Bg1 + 32);
        CPA_COMMIT();
        CPA_WAIT1();
    } else {
        CPA_WAIT0();
    }
    __syncthreads();

    for (int kt = 0; kt < nk; kt++) {
        const uint32_t buf = dbase + (kt % 3)*16384;
        const uint32_t bA = buf, bB = buf + 8192;
        #pragma unroll
        for (int ks = 0; ks < 2; ks++) {
            const int chunk = (ks << 1) + kc;
            uint32_t af[4][4];
            #pragma unroll
            for (int mi = 0; mi < 4; mi++) {
                uint32_t ad = bA + swoff(lrow_a + (mi << 4), chunk);
                LDMX4(af[mi][0], af[mi][1], af[mi][2], af[mi][3], ad);
            }
            uint32_t bf[4][2];
            #pragma unroll
            for (int bi = 0; bi < 2; bi++) {
                uint32_t t0, t1, t2, t3;
                uint32_t ad = bB + swoff(lrow_b + (bi << 4), chunk);
                LDMX4(t0, t1, t2, t3, ad);
                bf[bi*2  ][0] = t0; bf[bi*2+1][0] = t1;
                bf[bi*2  ][1] = t2; bf[bi*2+1][1] = t3;
            }
            #pragma unroll
            for (int mi = 0; mi < 4; mi++)
                #pragma unroll
                for (int nj = 0; nj < 4; nj++)
                    MMA16816(acc[mi][nj], af[mi], bf[nj][0], bf[nj][1]);
        }
        if (kt + 1 < nk) {
            if (kt + 2 < nk) {
                const int ko = (kt + 2) << 5;
                const uint32_t nb = dbase + ((kt + 2) % 3)*16384;
                CPA16(nb + so0,        Ag0 + ko); CPA16(nb + so1,        Ag1 + ko);
                CPA16(nb + 8192 + so0, Bg0 + ko); CPA16(nb + 8192 + so1, Bg1 + ko);
                CPA_COMMIT();
                CPA_WAIT1();
            } else {
                CPA_WAIT0();
            }
            __syncthreads();
        }
    }

    const int q  = lane >> 2;
    const int c2 = (lane & 3) << 1;
    #pragma unroll
    for (int mi = 0; mi < 4; mi++) {
        #pragma unroll
        for (int nj = 0; nj < 4; nj++) {
            const int col  = bn + wn + (nj << 3) + c2;
            const int row  = bm + wm + (mi << 4) + q;
            float b0v = bias[col], b1v = bias[col+1];
            float v0 = acc[mi][nj][0] + b0v;
            float v1 = acc[mi][nj][1] + b1v;
            float v2 = acc[mi][nj][2] + b0v;
            float v3 = acc[mi][nj][3] + b1v;
            if (act == 1) {
                v0 = fmaxf(v0, 0.f); v0 *= v0;
                v1 = fmaxf(v1, 0.f); v1 *= v1;
                v2 = fmaxf(v2, 0.f); v2 *= v2;
                v3 = fmaxf(v3, 0.f); v3 *= v3;
            }
            *(float2*)&C[(size_t)row*N + col]       = make_float2(v0, v1);
            *(float2*)&C[(size_t)(row + 8)*N + col] = make_float2(v2, v3);
        }
    }
}

// ---------------- 1) embedding gather + smear -> x_e3 (+ zero cnt/h0) --------
__global__ void __launch_bounds__(256) embed_kernel(
    const int* __restrict__ ids, const float* __restrict__ table,
    const float* __restrict__ smear_w, const float* __restrict__ smear_lambda)
{
    const int bt  = blockIdx.x;
    const int tid = threadIdx.x;
    if (tid == 0 && bt < NT)    g_cnt[bt] = 0;
    if (tid == 1 && bt < NB*NH) g_h[0][bt] = 0.f;

    const int t  = bt % NT;
    const int id = ids[bt];
    __shared__ float sgate;

    float v = 0.f;
    if (tid < 24) v = table[(size_t)id*NE + tid] * smear_w[tid];
    if (tid < 32) {
        #pragma unroll
        for (int off = 16; off; off >>= 1) v += __shfl_xor_sync(0xffffffffu, v, off);
        if (tid == 0) {
            float lam = smear_lambda[0];
            sgate = (t > 0) ? lam * (1.f/(1.f + __expf(-v))) : 0.f;
        }
    }
    __syncthreads();
    const float gate = sgate;
    const int idp = (t > 0) ? ids[bt-1] : 0;
    const float* rc = table + (size_t)id *NE;
    const float* rp = table + (size_t)idp*NE;
    __nv_bfloat16* dst = x_e3 + (size_t)bt*3*NE;
    for (int e = tid; e < NE; e += 256) {
        float x = rc[e] + gate*rp[e];
        __nv_bfloat16 h = __float2bfloat16(x);
        __nv_bfloat16 l = __float2bfloat16(x - __bfloat162float(h));
        dst[3*e] = h; dst[3*e+1] = h; dst[3*e+2] = l;
    }
}

// ---------------- persistent GRU scan: 16 warps, acquire-in-poll -------------
#define PACK2(out, lo, hi) \
    asm("mov.b64 %0, {%1, %2};" : "=l"(out) : "r"(__float_as_uint(lo)), "r"(__float_as_uint(hi)))
#define UNPACK2(lo, hi, in) do { uint32_t _a, _b; \
    asm("mov.b64 {%0, %1}, %2;" : "=r"(_a), "=r"(_b) : "l"(in)); \
    lo = __uint_as_float(_a); hi = __uint_as_float(_b); } while(0)
#define FMA2(acc, a, b) \
    asm("fma.rn.f32x2 %0, %1, %2, %0;" : "+l"(acc) : "l"(a), "l"(b))

__global__ void __launch_bounds__(512) gru_kernel(
    const float* __restrict__ w_hh, const float* __restrict__ b_hh)
{
    __shared__ __align__(16) float sh[2*NH];
    const int tid  = threadIdx.x;
    const int lane = tid & 31, w = tid >> 5;
    const int jj   = w >> 1, bb = w & 1;
    const int j    = (blockIdx.x << 3) + jj;

    unsigned long long wpk[3][16];
    #pragma unroll
    for (int g2 = 0; g2 < 3; g2++) {
        const float4* src = (const float4*)(w_hh + ((size_t)g2*NH + j)*NH);
        #pragma unroll
        for (int i = 0; i < 8; i++) {
            float4 v = src[i*32 + lane];
            PACK2(wpk[g2][2*i],   v.x, v.y);
            PACK2(wpk[g2][2*i+1], v.z, v.w);
        }
    }
    float bh_r = 0.f, bh_z = 0.f, bh_n = 0.f;
    if (lane == 0) { bh_r = b_hh[j]; bh_z = b_hh[NH + j]; bh_n = b_hh[2*NH + j]; }

    const ulonglong2* sbb = (const ulonglong2*)(sh + bb*NH);

    for (int t = 0; t < NT; t++) {
        // x prefetch: lanes 0..2 hold the 3 gate inputs for (bb, j)
        float xv = 0.f;
        if (lane < 3)
            xv = g_xproj[((size_t)(bb*NT + t))*(3*NH) + lane*NH + j];

        if (t > 0) {   // warp 0: ACQUIRE-poll (no separate acquire round trip)
            if (tid < 32) {
                const int* cp = g_cnt + (t-1);
                int v;
                do {
                    asm volatile("ld.acquire.gpu.global.s32 %0, [%1];"
                                 : "=r"(v) : "l"(cp) : "memory");
                } while (v < GRU_CTAS);
            }
            __syncthreads();
        }
        {   // stage h(t): 512 threads x 1 float4 = 2048 floats
            float4 hv = __ldcg((const float4*)g_h[t & 1] + tid);
            ((float4*)sh)[tid] = hv;
        }
        __syncthreads();

        // 3 packed dot products (this warp's batch only) over 1024
        unsigned long long a_r = 0ull, a_z = 0ull, a_n = 0ull;
        #pragma unroll
        for (int ii = 0; ii < 8; ii++) {
            ulonglong2 h2 = sbb[ii*32 + lane];
            FMA2(a_r, wpk[0][2*ii], h2.x); FMA2(a_r, wpk[0][2*ii+1], h2.y);
            FMA2(a_z, wpk[1][2*ii], h2.x); FMA2(a_z, wpk[1][2*ii+1], h2.y);
            FMA2(a_n, wpk[2][2*ii], h2.x); FMA2(a_n, wpk[2][2*ii+1], h2.y);
        }
        float t0, t1;
        UNPACK2(t0, t1, a_r); float sr = t0 + t1;
        UNPACK2(t0, t1, a_z); float sz = t0 + t1;
        UNPACK2(t0, t1, a_n); float sn = t0 + t1;
        #pragma unroll
        for (int off = 16; off; off >>= 1) {
            sr += __shfl_xor_sync(0xffffffffu, sr, off);
            sz += __shfl_xor_sync(0xffffffffu, sz, off);
            sn += __shfl_xor_sync(0xffffffffu, sn, off);
        }
        float xr = __shfl_sync(0xffffffffu, xv, 0);
        float xz = __shfl_sync(0xffffffffu, xv, 1);
        float xn = __shfl_sync(0xffffffffu, xv, 2);
        float hnew = 0.f;
        if (lane == 0) {
            float rr = 1.f/(1.f + __expf(-(xr + sr + bh_r)));
            float zz = 1.f/(1.f + __expf(-(xz + sz + bh_z)));
            float nn = tanhf(xn + rr*(sn + bh_n));
            float hold = sh[bb*NH + j];
            hnew = (1.f - zz)*nn + zz*hold;
            __stcg(&g_h[(t+1) & 1][bb*NH + j], hnew);   // ONLY h before release
        }
        __syncthreads();
        if (tid == 0) {
            asm volatile("red.release.gpu.global.add.s32 [%0], %1;"
                         :: "l"(g_cnt + t), "r"(1) : "memory");
        }
        // deferred bulk stores (off the cross-CTA critical path)
        if (lane == 0) {
            g_states[((size_t)(bb*NT + t))*NH + j] = hnew;
            __nv_bfloat16 hh = __float2bfloat16(hnew);
            __nv_bfloat16 hl = __float2bfloat16(hnew - __bfloat162float(hh));
            __nv_bfloat16* s3 = x_s3 + ((size_t)(bb*NT + t))*(3*NH) + 3*j;
            s3[0] = hh; s3[1] = hh; s3[2] = hl;
        }
    }
}

// ---------------- bias concat for fused q/k GEMM ------------------------------
__global__ void concat_bias(const float* __restrict__ bq, const float* __restrict__ bk)
{
    int i = threadIdx.x;
    g_bqk[i] = (i < NM) ? bq[i] : bk[i - NM];
}

// ---------------- g = sigmoid(states @ wg^T + bg) ----------------------------
__global__ void __launch_bounds__(256) g_kernel(
    const float* __restrict__ wg, const float* __restrict__ bg)
{
    const int row  = (blockIdx.x << 3) + (threadIdx.x >> 5);
    const int lane = threadIdx.x & 31;
    const float* s = g_states + (size_t)row*NH;
    float acc = 0.f;
    #pragma unroll 8
    for (int i = 0; i < 32; i++) acc += s[lane + (i<<5)] * wg[lane + (i<<5)];
    #pragma unroll
    for (int off = 16; off; off >>= 1) acc += __shfl_xor_sync(0xffffffffu, acc, off);
    if (lane == 0) g_gate[row] = 1.f/(1.f + __expf(-(acc + bg[0])));
}

// ---------------- causal attention + fused vocab scatter ---------------------
__global__ void __launch_bounds__(256) attn_kernel(
    const int* __restrict__ ids, float* __restrict__ out,
    const float* __restrict__ mscale_p)
{
    const int t = blockIdx.x;
    const int b = blockIdx.y;
    if (t == 0) return;

    __shared__ float sc[NT];
    __shared__ __align__(16) float qs[NM];
    __shared__ float red[8];
    const int tid = threadIdx.x;
    const int lane = tid & 31, wp = tid >> 5;

    if (tid < NM) qs[tid] = g_qk[((size_t)(b*NT + t))*(2*NM) + tid];
    __syncthreads();
    const float4* q4 = (const float4*)qs;

    float lmax = -1e30f;
    for (int s = tid; s < t; s += 256) {
        const float4* k4 = (const float4*)(g_qk + ((size_t)(b*NT + s))*(2*NM) + NM);
        float acc = 0.f;
        #pragma unroll
        for (int c = 0; c < 32; c++) {
            float4 qv = q4[c]; float4 kv = k4[c];
            acc += qv.x*kv.x + qv.y*kv.y + qv.z*kv.z + qv.w*kv.w;
        }
        acc *= 0.0883883476483184f;
        sc[s] = acc;
        lmax = fmaxf(lmax, acc);
    }
    #pragma unroll
    for (int off = 16; off; off >>= 1) lmax = fmaxf(lmax, __shfl_xor_sync(0xffffffffu, lmax, off));
    if (lane == 0) red[wp] = lmax;
    __syncthreads();
    if (tid == 0) {
        float m = red[0];
        #pragma unroll
        for (int i = 1; i < 8; i++) m = fmaxf(m, red[i]);
        red[0] = m;
    }
    __syncthreads();
    const float smax = red[0];
    __syncthreads();

    float lsum = 0.f;
    for (int s = tid; s < t; s += 256) {
        float e = __expf(sc[s] - smax);
        sc[s] = e;
        lsum += e;
    }
    #pragma unroll
    for (int off = 16; off; off >>= 1) lsum += __shfl_xor_sync(0xffffffffu, lsum, off);
    if (lane == 0) red[wp] = lsum;
    __syncthreads();
    if (tid == 0) {
        float ssum = 0.f;
        #pragma unroll
        for (int i = 0; i < 8; i++) ssum += red[i];
        red[0] = ssum;
    }
    __syncthreads();
    const float ssum = fmaxf(red[0], 1e-6f);
    const float scale = g_gate[b*NT + t] * mscale_p[0] / ssum;

    float* orow = out + ((size_t)(b*NT + t))*NV;
    const int* idr = ids + b*NT;
    for (int s = tid; s < t; s += 256)
        atomicAdd(&orow[idr[s]], sc[s]*scale);
}

// ---------------- launcher ----------------------------------------------------
extern "C" void kernel_launch(void* const* d_in, const int* in_sizes, int n_in,
                              void* d_out, int out_size)
{
    const int*   ids     = (const int*)  d_in[0];
    const float* table   = (const float*)d_in[1];
    const float* w_ih    = (const float*)d_in[2];
    const float* w_hh    = (const float*)d_in[3];
    const float* b_ih    = (const float*)d_in[4];
    const float* b_hh    = (const float*)d_in[5];
    const float* wq      = (const float*)d_in[6];
    const float* bq      = (const float*)d_in[7];
    const float* wk      = (const float*)d_in[8];
    const float* bk      = (const float*)d_in[9];
    const float* wg      = (const float*)d_in[10];
    const float* bg      = (const float*)d_in[11];
    const float* w_fc    = (const float*)d_in[12];
    const float* b_fc    = (const float*)d_in[13];
    const float* w_proj  = (const float*)d_in[14];
    const float* b_proj  = (const float*)d_in[15];
    const float* out_b   = (const float*)d_in[16];
    const float* mscale  = (const float*)d_in[17];
    const float* smear_w = (const float*)d_in[18];
    const float* smear_l = (const float*)d_in[19];
    float* out = (float*)d_out;
    (void)in_sizes; (void)n_in; (void)out_size;

    void *p_xproj, *p_states, *p_head, *p_bfeat, *p_qk, *p_bqkv;
    void *p_e3, *p_wih3, *p_s3, *p_wfc3, *p_hd3, *p_wp3, *p_f3, *p_t3, *p_wqk3;
    cudaGetSymbolAddress(&p_xproj,  g_xproj);
    cudaGetSymbolAddress(&p_states, g_states);
    cudaGetSymbolAddress(&p_head,   g_head);
    cudaGetSymbolAddress(&p_bfeat,  g_bfeat);
    cudaGetSymbolAddress(&p_qk,     g_qk);
    cudaGetSymbolAddress(&p_bqkv,   g_bqk);
    cudaGetSymbolAddress(&p_e3,     x_e3);
    cudaGetSymbolAddress(&p_wih3,   x_wih3);
    cudaGetSymbolAddress(&p_s3,     x_s3);
    cudaGetSymbolAddress(&p_wfc3,   x_wfc3);
    cudaGetSymbolAddress(&p_hd3,    x_hd3);
    cudaGetSymbolAddress(&p_wp3,    x_wp3);
    cudaGetSymbolAddress(&p_f3,     x_f3);
    cudaGetSymbolAddress(&p_t3,     x_t3);
    cudaGetSymbolAddress(&p_wqk3,   x_wqk3);

    cudaFuncSetAttribute(hmma_gemm, cudaFuncAttributeMaxDynamicSharedMemorySize, GEMM_SMEM);

    #define EXPAND(srcp, dstp, nelem, mode) \
        expand3_kernel<<<((nelem)/8 + 255)/256, 256>>>((const float*)(srcp), (__nv_bfloat16*)(dstp), (nelem)/8, mode)

    // 1) embedding + smear -> x_e3 (+ zero barrier counters and h0)
    embed_kernel<<<NROW, 256>>>(ids, table, smear_w, smear_l);
    // 2) x_proj = emb @ w_ih^T + b_ih        [4096,3072], K3=1536
    EXPAND(w_ih,  p_wih3, 3*NH*NE,      1);
    hmma_gemm<<<dim3(24,32), 256, GEMM_SMEM>>>((const __nv_bfloat16*)p_e3, (const __nv_bfloat16*)p_wih3,
                                               b_ih, (float*)p_xproj, NROW, 3*NH, 3*NE, 0);
    // 3) GRU scan -> g_states + x_s3 (acquire-in-poll)
    gru_kernel<<<GRU_CTAS, 512>>>(w_hh, b_hh);
    // 4) head = relu^2(states @ w_fc^T + b_fc)  [4096,2048], K3=3072
    EXPAND(w_fc,     p_wfc3, 4*NE*NH,   1);
    hmma_gemm<<<dim3(16,32), 256, GEMM_SMEM>>>((const __nv_bfloat16*)p_s3, (const __nv_bfloat16*)p_wfc3,
                                               b_fc, (float*)p_head, NROW, 4*NE, 3*NH, 1);
    // 5) base_feat = head @ w_proj^T + b_proj   [4096,512], K3=6144
    EXPAND(p_head, p_hd3, NROW*4*NE,    0);
    EXPAND(w_proj, p_wp3, NE*4*NE,      1);
    hmma_gemm<<<dim3(4,32), 256, GEMM_SMEM>>>((const __nv_bfloat16*)p_hd3, (const __nv_bfloat16*)p_wp3,
                                              b_proj, (float*)p_bfeat, NROW, NE, 3*4*NE, 0);
    // 6) logits = base_feat @ emb_table^T + out_b -> d_out [4096,32000], K3=1536
    EXPAND(p_bfeat, p_f3, NROW*NE,      0);
    EXPAND(table,   p_t3, NV*NE,        1);
    hmma_gemm<<<dim3(250,32), 256, GEMM_SMEM>>>((const __nv_bfloat16*)p_f3, (const __nv_bfloat16*)p_t3,
                                                out_b, out, NROW, NV, 3*NE, 0);
    // 7) fused q/k GEMM: [4096, 256], K3=3072
    EXPAND(wq, p_wqk3, NM*NH, 1);
    EXPAND(wk, (__nv_bfloat16*)p_wqk3 + (size_t)NM*3*NH, NM*NH, 1);
    concat_bias<<<1, 2*NM>>>(bq, bk);
    hmma_gemm<<<dim3(2,32), 256, GEMM_SMEM>>>((const __nv_bfloat16*)p_s3, (const __nv_bfloat16*)p_wqk3,
                                              (const float*)p_bqkv, (float*)p_qk, NROW, 2*NM, 3*NH, 0);
    // 8) g = sigmoid(states @ wg^T + bg)
    g_kernel<<<NROW/8, 256>>>(wg, bg);
    // 9) causal attention + scatter-add into d_out
    attn_kernel<<<dim3(NT, NB), 256>>>(ids, out, mscale);
    #undef EXPAND
}

// round 15
// speedup vs baseline: 1.0137x; 1.0137x over previous
#include <cuda_runtime.h>
#include <cuda_bf16.h>
#include <cstdint>

#define NB 2
#define NT 2048
#define NV 32000
#define NE 512
#define NH 1024
#define NM 128
#define NROW (NB*NT)      // 4096
#define GRU_CTAS 128

// ---------------- scratch (module-static device memory; no cudaMalloc) -------
__device__ __align__(16) float g_xproj[(size_t)NROW*3*NH];
__device__ __align__(16) float g_states[(size_t)NROW*NH];
__device__ __align__(16) float g_qk[(size_t)NROW*2*NM];
__device__ __align__(16) float g_bqk[2*NM];
__device__ __align__(16) float g_gate[NROW];
__device__ __align__(16) float g_h[2][NB*NH];      // double-buffered GRU state
__device__ int g_cnt[NT];                          // per-step barrier counters

// bf16 triple-expanded operands (K' = 3K)
__device__ __align__(16) __nv_bfloat16 x_e3  [(size_t)NROW*3*NE];
__device__ __align__(16) __nv_bfloat16 x_wih3[(size_t)3*NH*3*NE];
__device__ __align__(16) __nv_bfloat16 x_s3  [(size_t)NROW*3*NH];
__device__ __align__(16) __nv_bfloat16 x_wfc3[(size_t)4*NE*3*NH];
__device__ __align__(16) __nv_bfloat16 x_hd3 [(size_t)NROW*3*4*NE];
__device__ __align__(16) __nv_bfloat16 x_wp3 [(size_t)NE*3*4*NE];
__device__ __align__(16) __nv_bfloat16 x_f3  [(size_t)NROW*3*NE];
__device__ __align__(16) __nv_bfloat16 x_t3  [(size_t)NV*3*NE];
__device__ __align__(16) __nv_bfloat16 x_wqk3[(size_t)2*NM*3*NH];

// ---------------- operand expansion: fp32 -> triple bf16 ---------------------
__global__ void __launch_bounds__(256) expand3_kernel(
    const float* __restrict__ src, __nv_bfloat16* __restrict__ dst, int n8, int bmode)
{
    int i = blockIdx.x*256 + threadIdx.x;
    if (i >= n8) return;
    const float4* s4 = (const float4*)src + (size_t)i*2;
    float4 v0 = s4[0], v1 = s4[1];
    float a[8] = {v0.x, v0.y, v0.z, v0.w, v1.x, v1.y, v1.z, v1.w};
    __align__(16) __nv_bfloat16 o[24];
    #pragma unroll
    for (int j = 0; j < 8; j++) {
        float x = a[j];
        __nv_bfloat16 h = __float2bfloat16(x);
        __nv_bfloat16 l = __float2bfloat16(x - __bfloat162float(h));
        if (bmode) { o[3*j] = h; o[3*j+1] = l; o[3*j+2] = h; }
        else       { o[3*j] = h; o[3*j+1] = h; o[3*j+2] = l; }
    }
    uint4* d4 = (uint4*)(dst + (size_t)i*24);
    const uint4* ov = (const uint4*)o;
    d4[0] = ov[0]; d4[1] = ov[1]; d4[2] = ov[2];
}

// ================= HMMA (mma.sync) bf16 GEMM + 3-stage cp.async =============
__device__ __forceinline__ uint32_t smem_u32(const void* p) {
    uint32_t a;
    asm("{ .reg .u64 t; cvta.to.shared.u64 t, %1; cvt.u32.u64 %0, t; }" : "=r"(a) : "l"(p));
    return a;
}

__device__ __forceinline__ int swoff(int row, int ch) {
    int p = row >> 1;
    return (p << 7) + (((((row & 1) << 2) | ch) ^ (p & 7)) << 4);
}

#define CPA16(dst, src) \
    asm volatile("cp.async.cg.shared.global [%0], [%1], 16;" :: "r"(dst), "l"(src) : "memory")
#define CPA_COMMIT() asm volatile("cp.async.commit_group;" ::: "memory")
#define CPA_WAIT0()  asm volatile("cp.async.wait_group 0;"  ::: "memory")
#define CPA_WAIT1()  asm volatile("cp.async.wait_group 1;"  ::: "memory")

#define LDMX4(r0,r1,r2,r3, addr) \
    asm volatile("ldmatrix.sync.aligned.m8n8.x4.shared.b16 {%0,%1,%2,%3}, [%4];" \
        : "=r"(r0),"=r"(r1),"=r"(r2),"=r"(r3) : "r"(addr))

#define MMA16816(d, a, b0v, b1v) \
    asm volatile("mma.sync.aligned.m16n8k16.row.col.f32.bf16.bf16.f32 " \
        "{%0,%1,%2,%3}, {%4,%5,%6,%7}, {%8,%9}, {%0,%1,%2,%3};" \
        : "+f"((d)[0]),"+f"((d)[1]),"+f"((d)[2]),"+f"((d)[3]) \
        : "r"((a)[0]),"r"((a)[1]),"r"((a)[2]),"r"((a)[3]), "r"(b0v),"r"(b1v))

#define GEMM_SMEM (49152 + 1024)

// pack two fp32 values (cols col, col+1) into a 6-bf16 triple-A-mode run
__device__ __forceinline__ void store_triple2(__nv_bfloat16* p, float a, float b) {
    __nv_bfloat16 ha = __float2bfloat16(a);
    __nv_bfloat16 la = __float2bfloat16(a - __bfloat162float(ha));
    __nv_bfloat16 hb = __float2bfloat16(b);
    __nv_bfloat16 lb = __float2bfloat16(b - __bfloat162float(hb));
    uint32_t w0 = ((uint32_t)__bfloat16_as_ushort(ha) << 16) | __bfloat16_as_ushort(ha);
    uint32_t w1 = ((uint32_t)__bfloat16_as_ushort(hb) << 16) | __bfloat16_as_ushort(la);
    uint32_t w2 = ((uint32_t)__bfloat16_as_ushort(lb) << 16) | __bfloat16_as_ushort(hb);
    uint32_t* q = (uint32_t*)p;          // byte offset 6*col, col even -> 4B aligned
    q[0] = w0; q[1] = w1; q[2] = w2;
}

// act: 0 plain fp32, 1 relu^2 fp32, 2 triple-bf16, 3 relu^2 + triple-bf16
__global__ void __launch_bounds__(256) hmma_gemm(
    const __nv_bfloat16* __restrict__ A, const __nv_bfloat16* __restrict__ B,
    const float* __restrict__ bias, float* __restrict__ C,
    int M, int N, int K3, int act)
{
    extern __shared__ char dsm_raw[];
    const uint32_t draw  = smem_u32(dsm_raw);
    const uint32_t dbase = (draw + 1023) & ~1023u;

    const int tid  = threadIdx.x;
    const int lane = tid & 31, wid = tid >> 5;

    // CTA rasterization swizzle: GM=8 M-tiles per launch-order group.
    const int nbn = gridDim.x;
    const int bid = blockIdx.y * nbn + blockIdx.x;
    const int grp = bid / (nbn << 3);
    const int rem = bid - grp * (nbn << 3);
    const int bm  = ((grp << 3) + (rem & 7)) << 7;
    const int bn  = (rem >> 3) << 7;

    const int wm = (wid >> 2) << 6;
    const int wn = (wid & 3) << 5;

    const int row0 = tid >> 2,         ch0 = tid & 3;
    const int row1 = (tid + 256) >> 2, ch1 = tid & 3;
    const int so0 = swoff(row0, ch0), so1 = swoff(row1, ch1);
    const __nv_bfloat16* Ag0 = A + (size_t)(bm + row0)*K3 + ch0*8;
    const __nv_bfloat16* Ag1 = A + (size_t)(bm + row1)*K3 + ch1*8;
    const __nv_bfloat16* Bg0 = B + (size_t)(bn + row0)*K3 + ch0*8;
    const __nv_bfloat16* Bg1 = B + (size_t)(bn + row1)*K3 + ch1*8;

    const int g = lane >> 3, rr = lane & 7;
    const int lrow_a = wm + ((g & 1) << 3) + rr;
    const int lrow_b = wn + ((g & 1) << 3) + rr;
    const int kc = g >> 1;

    float acc[4][4][4];
    #pragma unroll
    for (int i = 0; i < 4; i++)
        #pragma unroll
        for (int j = 0; j < 4; j++)
            #pragma unroll
            for (int r = 0; r < 4; r++) acc[i][j][r] = 0.f;

    const int nk = K3 >> 5;
    {
        const uint32_t sA = dbase, sB = dbase + 8192;
        CPA16(sA + so0, Ag0); CPA16(sA + so1, Ag1);
        CPA16(sB + so0, Bg0); CPA16(sB + so1, Bg1);
        CPA_COMMIT();
    }
    if (nk > 1) {
        const uint32_t sA = dbase + 16384, sB = dbase + 16384 + 8192;
        CPA16(sA + so0, Ag0 + 32); CPA16(sA + so1, Ag1 + 32);
        CPA16(sB + so0, Bg0 + 32); CPA16(sB + so1, Bg1 + 32);
        CPA_COMMIT();
        CPA_WAIT1();
    } else {
        CPA_WAIT0();
    }
    __syncthreads();

    for (int kt = 0; kt < nk; kt++) {
        const uint32_t buf = dbase + (kt % 3)*16384;
        const uint32_t bA = buf, bB = buf + 8192;
        #pragma unroll
        for (int ks = 0; ks < 2; ks++) {
            const int chunk = (ks << 1) + kc;
            uint32_t af[4][4];
            #pragma unroll
            for (int mi = 0; mi < 4; mi++) {
                uint32_t ad = bA + swoff(lrow_a + (mi << 4), chunk);
                LDMX4(af[mi][0], af[mi][1], af[mi][2], af[mi][3], ad);
            }
            uint32_t bf[4][2];
            #pragma unroll
            for (int bi = 0; bi < 2; bi++) {
                uint32_t t0, t1, t2, t3;
                uint32_t ad = bB + swoff(lrow_b + (bi << 4), chunk);
                LDMX4(t0, t1, t2, t3, ad);
                bf[bi*2  ][0] = t0; bf[bi*2+1][0] = t1;
                bf[bi*2  ][1] = t2; bf[bi*2+1][1] = t3;
            }
            #pragma unroll
            for (int mi = 0; mi < 4; mi++)
                #pragma unroll
                for (int nj = 0; nj < 4; nj++)
                    MMA16816(acc[mi][nj], af[mi], bf[nj][0], bf[nj][1]);
        }
        if (kt + 1 < nk) {
            if (kt + 2 < nk) {
                const int ko = (kt + 2) << 5;
                const uint32_t nb = dbase + ((kt + 2) % 3)*16384;
                CPA16(nb + so0,        Ag0 + ko); CPA16(nb + so1,        Ag1 + ko);
                CPA16(nb + 8192 + so0, Bg0 + ko); CPA16(nb + 8192 + so1, Bg1 + ko);
                CPA_COMMIT();
                CPA_WAIT1();
            } else {
                CPA_WAIT0();
            }
            __syncthreads();
        }
    }

    const int q  = lane >> 2;
    const int c2 = (lane & 3) << 1;
    #pragma unroll
    for (int mi = 0; mi < 4; mi++) {
        #pragma unroll
        for (int nj = 0; nj < 4; nj++) {
            const int col  = bn + wn + (nj << 3) + c2;
            const int row  = bm + wm + (mi << 4) + q;
            float b0v = bias[col], b1v = bias[col+1];
            float v0 = acc[mi][nj][0] + b0v;
            float v1 = acc[mi][nj][1] + b1v;
            float v2 = acc[mi][nj][2] + b0v;
            float v3 = acc[mi][nj][3] + b1v;
            if (act & 1) {
                v0 = fmaxf(v0, 0.f); v0 *= v0;
                v1 = fmaxf(v1, 0.f); v1 *= v1;
                v2 = fmaxf(v2, 0.f); v2 *= v2;
                v3 = fmaxf(v3, 0.f); v3 *= v3;
            }
            if (act < 2) {
                *(float2*)&C[(size_t)row*N + col]       = make_float2(v0, v1);
                *(float2*)&C[(size_t)(row + 8)*N + col] = make_float2(v2, v3);
            } else {   // fused triple-bf16 A-mode output (row stride 3N)
                __nv_bfloat16* Cb = (__nv_bfloat16*)C;
                store_triple2(Cb + (size_t)row*3*N       + 3*col, v0, v1);
                store_triple2(Cb + (size_t)(row + 8)*3*N + 3*col, v2, v3);
            }
        }
    }
}

// ---------------- 1) embedding gather + smear -> x_e3 (+ zero cnt/h0) --------
__global__ void __launch_bounds__(256) embed_kernel(
    const int* __restrict__ ids, const float* __restrict__ table,
    const float* __restrict__ smear_w, const float* __restrict__ smear_lambda)
{
    const int bt  = blockIdx.x;
    const int tid = threadIdx.x;
    if (tid == 0 && bt < NT)    g_cnt[bt] = 0;
    if (tid == 1 && bt < NB*NH) g_h[0][bt] = 0.f;

    const int t  = bt % NT;
    const int id = ids[bt];
    __shared__ float sgate;

    float v = 0.f;
    if (tid < 24) v = table[(size_t)id*NE + tid] * smear_w[tid];
    if (tid < 32) {
        #pragma unroll
        for (int off = 16; off; off >>= 1) v += __shfl_xor_sync(0xffffffffu, v, off);
        if (tid == 0) {
            float lam = smear_lambda[0];
            sgate = (t > 0) ? lam * (1.f/(1.f + __expf(-v))) : 0.f;
        }
    }
    __syncthreads();
    const float gate = sgate;
    const int idp = (t > 0) ? ids[bt-1] : 0;
    const float* rc = table + (size_t)id *NE;
    const float* rp = table + (size_t)idp*NE;
    __nv_bfloat16* dst = x_e3 + (size_t)bt*3*NE;
    for (int e = tid; e < NE; e += 256) {
        float x = rc[e] + gate*rp[e];
        __nv_bfloat16 h = __float2bfloat16(x);
        __nv_bfloat16 l = __float2bfloat16(x - __bfloat162float(h));
        dst[3*e] = h; dst[3*e+1] = h; dst[3*e+2] = l;
    }
}

// ---------------- persistent GRU scan: 16 warps (R13/R11 proven sync) --------
#define PACK2(out, lo, hi) \
    asm("mov.b64 %0, {%1, %2};" : "=l"(out) : "r"(__float_as_uint(lo)), "r"(__float_as_uint(hi)))
#define UNPACK2(lo, hi, in) do { uint32_t _a, _b; \
    asm("mov.b64 {%0, %1}, %2;" : "=r"(_a), "=r"(_b) : "l"(in)); \
    lo = __uint_as_float(_a); hi = __uint_as_float(_b); } while(0)
#define FMA2(acc, a, b) \
    asm("fma.rn.f32x2 %0, %1, %2, %0;" : "+l"(acc) : "l"(a), "l"(b))

__global__ void __launch_bounds__(512) gru_kernel(
    const float* __restrict__ w_hh, const float* __restrict__ b_hh)
{
    __shared__ __align__(16) float sh[2*NH];
    const int tid  = threadIdx.x;
    const int lane = tid & 31, w = tid >> 5;
    const int jj   = w >> 1, bb = w & 1;
    const int j    = (blockIdx.x << 3) + jj;

    unsigned long long wpk[3][16];
    #pragma unroll
    for (int g2 = 0; g2 < 3; g2++) {
        const float4* src = (const float4*)(w_hh + ((size_t)g2*NH + j)*NH);
        #pragma unroll
        for (int i = 0; i < 8; i++) {
            float4 v = src[i*32 + lane];
            PACK2(wpk[g2][2*i],   v.x, v.y);
            PACK2(wpk[g2][2*i+1], v.z, v.w);
        }
    }
    float bh_r = 0.f, bh_z = 0.f, bh_n = 0.f;
    if (lane == 0) { bh_r = b_hh[j]; bh_z = b_hh[NH + j]; bh_n = b_hh[2*NH + j]; }

    const ulonglong2* sbb = (const ulonglong2*)(sh + bb*NH);

    for (int t = 0; t < NT; t++) {
        // x prefetch: lanes 0..2 hold the 3 gate inputs for (bb, j)
        float xv = 0.f;
        if (lane < 3)
            xv = g_xproj[((size_t)(bb*NT + t))*(3*NH) + lane*NH + j];

        if (t > 0) {   // warp 0: relaxed poll, then single acquire
            if (tid < 32) {
                const int* cp = g_cnt + (t-1);
                int v;
                do {
                    asm volatile("ld.relaxed.gpu.global.s32 %0, [%1];"
                                 : "=r"(v) : "l"(cp) : "memory");
                } while (v < GRU_CTAS);
                asm volatile("ld.acquire.gpu.global.s32 %0, [%1];"
                             : "=r"(v) : "l"(cp) : "memory");
            }
            __syncthreads();
        }
        {   // stage h(t): 512 threads x 1 float4 = 2048 floats
            float4 hv = __ldcg((const float4*)g_h[t & 1] + tid);
            ((float4*)sh)[tid] = hv;
        }
        __syncthreads();

        // 3 packed dot products (this warp's batch only) over 1024
        unsigned long long a_r = 0ull, a_z = 0ull, a_n = 0ull;
        #pragma unroll
        for (int ii = 0; ii < 8; ii++) {
            ulonglong2 h2 = sbb[ii*32 + lane];
            FMA2(a_r, wpk[0][2*ii], h2.x); FMA2(a_r, wpk[0][2*ii+1], h2.y);
            FMA2(a_z, wpk[1][2*ii], h2.x); FMA2(a_z, wpk[1][2*ii+1], h2.y);
            FMA2(a_n, wpk[2][2*ii], h2.x); FMA2(a_n, wpk[2][2*ii+1], h2.y);
        }
        float t0, t1;
        UNPACK2(t0, t1, a_r); float sr = t0 + t1;
        UNPACK2(t0, t1, a_z); float sz = t0 + t1;
        UNPACK2(t0, t1, a_n); float sn = t0 + t1;
        #pragma unroll
        for (int off = 16; off; off >>= 1) {
            sr += __shfl_xor_sync(0xffffffffu, sr, off);
            sz += __shfl_xor_sync(0xffffffffu, sz, off);
            sn += __shfl_xor_sync(0xffffffffu, sn, off);
        }
        float xr = __shfl_sync(0xffffffffu, xv, 0);
        float xz = __shfl_sync(0xffffffffu, xv, 1);
        float xn = __shfl_sync(0xffffffffu, xv, 2);
        float hnew = 0.f;
        if (lane == 0) {
            float rr = 1.f/(1.f + __expf(-(xr + sr + bh_r)));
            float zz = 1.f/(1.f + __expf(-(xz + sz + bh_z)));
            float nn = tanhf(xn + rr*(sn + bh_n));
            float hold = sh[bb*NH + j];
            hnew = (1.f - zz)*nn + zz*hold;
            __stcg(&g_h[(t+1) & 1][bb*NH + j], hnew);   // ONLY h before release
        }
        __syncthreads();
        if (tid == 0) {
            asm volatile("red.release.gpu.global.add.s32 [%0], %1;"
                         :: "l"(g_cnt + t), "r"(1) : "memory");
        }
        // deferred bulk stores (off the cross-CTA critical path)
        if (lane == 0) {
            g_states[((size_t)(bb*NT + t))*NH + j] = hnew;
            __nv_bfloat16 hh = __float2bfloat16(hnew);
            __nv_bfloat16 hl = __float2bfloat16(hnew - __bfloat162float(hh));
            __nv_bfloat16* s3 = x_s3 + ((size_t)(bb*NT + t))*(3*NH) + 3*j;
            s3[0] = hh; s3[1] = hh; s3[2] = hl;
        }
    }
}

// ---------------- bias concat for fused q/k GEMM ------------------------------
__global__ void concat_bias(const float* __restrict__ bq, const float* __restrict__ bk)
{
    int i = threadIdx.x;
    g_bqk[i] = (i < NM) ? bq[i] : bk[i - NM];
}

// ---------------- g = sigmoid(states @ wg^T + bg) ----------------------------
__global__ void __launch_bounds__(256) g_kernel(
    const float* __restrict__ wg, const float* __restrict__ bg)
{
    const int row  = (blockIdx.x << 3) + (threadIdx.x >> 5);
    const int lane = threadIdx.x & 31;
    const float* s = g_states + (size_t)row*NH;
    float acc = 0.f;
    #pragma unroll 8
    for (int i = 0; i < 32; i++) acc += s[lane + (i<<5)] * wg[lane + (i<<5)];
    #pragma unroll
    for (int off = 16; off; off >>= 1) acc += __shfl_xor_sync(0xffffffffu, acc, off);
    if (lane == 0) g_gate[row] = 1.f/(1.f + __expf(-(acc + bg[0])));
}

// ---------------- causal attention + fused vocab scatter ---------------------
__global__ void __launch_bounds__(256) attn_kernel(
    const int* __restrict__ ids, float* __restrict__ out,
    const float* __restrict__ mscale_p)
{
    const int t = blockIdx.x;
    const int b = blockIdx.y;
    if (t == 0) return;

    __shared__ float sc[NT];
    __shared__ __align__(16) float qs[NM];
    __shared__ float red[8];
    const int tid = threadIdx.x;
    const int lane = tid & 31, wp = tid >> 5;

    if (tid < NM) qs[tid] = g_qk[((size_t)(b*NT + t))*(2*NM) + tid];
    __syncthreads();
    const float4* q4 = (const float4*)qs;

    float lmax = -1e30f;
    for (int s = tid; s < t; s += 256) {
        const float4* k4 = (const float4*)(g_qk + ((size_t)(b*NT + s))*(2*NM) + NM);
        float acc = 0.f;
        #pragma unroll
        for (int c = 0; c < 32; c++) {
            float4 qv = q4[c]; float4 kv = k4[c];
            acc += qv.x*kv.x + qv.y*kv.y + qv.z*kv.z + qv.w*kv.w;
        }
        acc *= 0.0883883476483184f;
        sc[s] = acc;
        lmax = fmaxf(lmax, acc);
    }
    #pragma unroll
    for (int off = 16; off; off >>= 1) lmax = fmaxf(lmax, __shfl_xor_sync(0xffffffffu, lmax, off));
    if (lane == 0) red[wp] = lmax;
    __syncthreads();
    if (tid == 0) {
        float m = red[0];
        #pragma unroll
        for (int i = 1; i < 8; i++) m = fmaxf(m, red[i]);
        red[0] = m;
    }
    __syncthreads();
    const float smax = red[0];
    __syncthreads();

    float lsum = 0.f;
    for (int s = tid; s < t; s += 256) {
        float e = __expf(sc[s] - smax);
        sc[s] = e;
        lsum += e;
    }
    #pragma unroll
    for (int off = 16; off; off >>= 1) lsum += __shfl_xor_sync(0xffffffffu, lsum, off);
    if (lane == 0) red[wp] = lsum;
    __syncthreads();
    if (tid == 0) {
        float ssum = 0.f;
        #pragma unroll
        for (int i = 0; i < 8; i++) ssum += red[i];
        red[0] = ssum;
    }
    __syncthreads();
    const float ssum = fmaxf(red[0], 1e-6f);
    const float scale = g_gate[b*NT + t] * mscale_p[0] / ssum;

    float* orow = out + ((size_t)(b*NT + t))*NV;
    const int* idr = ids + b*NT;
    for (int s = tid; s < t; s += 256)
        atomicAdd(&orow[idr[s]], sc[s]*scale);
}

// ---------------- launcher ----------------------------------------------------
extern "C" void kernel_launch(void* const* d_in, const int* in_sizes, int n_in,
                              void* d_out, int out_size)
{
    const int*   ids     = (const int*)  d_in[0];
    const float* table   = (const float*)d_in[1];
    const float* w_ih    = (const float*)d_in[2];
    const float* w_hh    = (const float*)d_in[3];
    const float* b_ih    = (const float*)d_in[4];
    const float* b_hh    = (const float*)d_in[5];
    const float* wq      = (const float*)d_in[6];
    const float* bq      = (const float*)d_in[7];
    const float* wk      = (const float*)d_in[8];
    const float* bk      = (const float*)d_in[9];
    const float* wg      = (const float*)d_in[10];
    const float* bg      = (const float*)d_in[11];
    const float* w_fc    = (const float*)d_in[12];
    const float* b_fc    = (const float*)d_in[13];
    const float* w_proj  = (const float*)d_in[14];
    const float* b_proj  = (const float*)d_in[15];
    const float* out_b   = (const float*)d_in[16];
    const float* mscale  = (const float*)d_in[17];
    const float* smear_w = (const float*)d_in[18];
    const float* smear_l = (const float*)d_in[19];
    float* out = (float*)d_out;
    (void)in_sizes; (void)n_in; (void)out_size;

    void *p_xproj, *p_states, *p_qk, *p_bqkv;
    void *p_e3, *p_wih3, *p_s3, *p_wfc3, *p_hd3, *p_wp3, *p_f3, *p_t3, *p_wqk3;
    cudaGetSymbolAddress(&p_xproj,  g_xproj);
    cudaGetSymbolAddress(&p_states, g_states);
    cudaGetSymbolAddress(&p_qk,     g_qk);
    cudaGetSymbolAddress(&p_bqkv,   g_bqk);
    cudaGetSymbolAddress(&p_e3,     x_e3);
    cudaGetSymbolAddress(&p_wih3,   x_wih3);
    cudaGetSymbolAddress(&p_s3,     x_s3);
    cudaGetSymbolAddress(&p_wfc3,   x_wfc3);
    cudaGetSymbolAddress(&p_hd3,    x_hd3);
    cudaGetSymbolAddress(&p_wp3,    x_wp3);
    cudaGetSymbolAddress(&p_f3,     x_f3);
    cudaGetSymbolAddress(&p_t3,     x_t3);
    cudaGetSymbolAddress(&p_wqk3,   x_wqk3);

    cudaFuncSetAttribute(hmma_gemm, cudaFuncAttributeMaxDynamicSharedMemorySize, GEMM_SMEM);

    #define EXPAND(srcp, dstp, nelem, mode) \
        expand3_kernel<<<((nelem)/8 + 255)/256, 256>>>((const float*)(srcp), (__nv_bfloat16*)(dstp), (nelem)/8, mode)

    // 1) embedding + smear -> x_e3 (+ zero barrier counters and h0)
    embed_kernel<<<NROW, 256>>>(ids, table, smear_w, smear_l);
    // 2) x_proj = emb @ w_ih^T + b_ih        [4096,3072], K3=1536
    EXPAND(w_ih,  p_wih3, 3*NH*NE,      1);
    hmma_gemm<<<dim3(24,32), 256, GEMM_SMEM>>>((const __nv_bfloat16*)p_e3, (const __nv_bfloat16*)p_wih3,
                                               b_ih, (float*)p_xproj, NROW, 3*NH, 3*NE, 0);
    // 3) GRU scan -> g_states + x_s3 (R13 proven sync)
    gru_kernel<<<GRU_CTAS, 512>>>(w_hh, b_hh);
    // 4) head = relu^2(states @ w_fc^T + b_fc) -> x_hd3 DIRECT (act=3)
    EXPAND(w_fc,     p_wfc3, 4*NE*NH,   1);
    hmma_gemm<<<dim3(16,32), 256, GEMM_SMEM>>>((const __nv_bfloat16*)p_s3, (const __nv_bfloat16*)p_wfc3,
                                               b_fc, (float*)p_hd3, NROW, 4*NE, 3*NH, 3);
    // 5) base_feat = head @ w_proj^T + b_proj -> x_f3 DIRECT (act=2)
    EXPAND(w_proj, p_wp3, NE*4*NE,      1);
    hmma_gemm<<<dim3(4,32), 256, GEMM_SMEM>>>((const __nv_bfloat16*)p_hd3, (const __nv_bfloat16*)p_wp3,
                                              b_proj, (float*)p_f3, NROW, NE, 3*4*NE, 2);
    // 6) logits = base_feat @ emb_table^T + out_b -> d_out [4096,32000], K3=1536
    EXPAND(table,   p_t3, NV*NE,        1);
    hmma_gemm<<<dim3(250,32), 256, GEMM_SMEM>>>((const __nv_bfloat16*)p_f3, (const __nv_bfloat16*)p_t3,
                                                out_b, out, NROW, NV, 3*NE, 0);
    // 7) fused q/k GEMM: [4096, 256], K3=3072
    EXPAND(wq, p_wqk3, NM*NH, 1);
    EXPAND(wk, (__nv_bfloat16*)p_wqk3 + (size_t)NM*3*NH, NM*NH, 1);
    concat_bias<<<1, 2*NM>>>(bq, bk);
    hmma_gemm<<<dim3(2,32), 256, GEMM_SMEM>>>((const __nv_bfloat16*)p_s3, (const __nv_bfloat16*)p_wqk3,
                                              (const float*)p_bqkv, (float*)p_qk, NROW, 2*NM, 3*NH, 0);
    // 8) g = sigmoid(states @ wg^T + bg)
    g_kernel<<<NROW/8, 256>>>(wg, bg);
    // 9) causal attention + scatter-add into d_out
    attn_kernel<<<dim3(NT, NB), 256>>>(ids, out, mscale);
    #undef EXPAND
}

// round 16
// speedup vs baseline: 1.0154x; 1.0017x over previous
#include <cuda_runtime.h>
#include <cuda_bf16.h>
#include <cstdint>

#define NB 2
#define NT 2048
#define NV 32000
#define NE 512
#define NH 1024
#define NM 128
#define NROW (NB*NT)      // 4096
#define GRU_CTAS 128

// ---------------- scratch (module-static device memory; no cudaMalloc) -------
__device__ __align__(16) float g_xproj[(size_t)NROW*3*NH];
__device__ __align__(16) float g_states[(size_t)NROW*NH];
__device__ __align__(16) float g_qk[(size_t)NROW*2*NM];
__device__ __align__(16) float g_bqk[2*NM];
__device__ __align__(16) float g_gate[NROW];
__device__ __align__(16) float g_h[2][NB*NH];      // double-buffered GRU state
__device__ int g_cnt[NT];                          // per-step barrier counters

// bf16 triple-expanded operands (K' = 3K)
__device__ __align__(16) __nv_bfloat16 x_e3  [(size_t)NROW*3*NE];
__device__ __align__(16) __nv_bfloat16 x_wih3[(size_t)3*NH*3*NE];
__device__ __align__(16) __nv_bfloat16 x_s3  [(size_t)NROW*3*NH];
__device__ __align__(16) __nv_bfloat16 x_wfc3[(size_t)4*NE*3*NH];
__device__ __align__(16) __nv_bfloat16 x_hd3 [(size_t)NROW*3*4*NE];
__device__ __align__(16) __nv_bfloat16 x_wp3 [(size_t)NE*3*4*NE];
__device__ __align__(16) __nv_bfloat16 x_f3  [(size_t)NROW*3*NE];
__device__ __align__(16) __nv_bfloat16 x_t3  [(size_t)NV*3*NE];
__device__ __align__(16) __nv_bfloat16 x_wqk3[(size_t)2*NM*3*NH];

// ---------------- operand expansion: fp32 -> triple bf16 ---------------------
__global__ void __launch_bounds__(256) expand3_kernel(
    const float* __restrict__ src, __nv_bfloat16* __restrict__ dst, int n8, int bmode)
{
    int i = blockIdx.x*256 + threadIdx.x;
    if (i >= n8) return;
    const float4* s4 = (const float4*)src + (size_t)i*2;
    float4 v0 = s4[0], v1 = s4[1];
    float a[8] = {v0.x, v0.y, v0.z, v0.w, v1.x, v1.y, v1.z, v1.w};
    __align__(16) __nv_bfloat16 o[24];
    #pragma unroll
    for (int j = 0; j < 8; j++) {
        float x = a[j];
        __nv_bfloat16 h = __float2bfloat16(x);
        __nv_bfloat16 l = __float2bfloat16(x - __bfloat162float(h));
        if (bmode) { o[3*j] = h; o[3*j+1] = l; o[3*j+2] = h; }
        else       { o[3*j] = h; o[3*j+1] = h; o[3*j+2] = l; }
    }
    uint4* d4 = (uint4*)(dst + (size_t)i*24);
    const uint4* ov = (const uint4*)o;
    d4[0] = ov[0]; d4[1] = ov[1]; d4[2] = ov[2];
}

// ================= HMMA (mma.sync) bf16 GEMM + 3-stage cp.async =============
__device__ __forceinline__ uint32_t smem_u32(const void* p) {
    uint32_t a;
    asm("{ .reg .u64 t; cvta.to.shared.u64 t, %1; cvt.u32.u64 %0, t; }" : "=r"(a) : "l"(p));
    return a;
}

__device__ __forceinline__ int swoff(int row, int ch) {
    int p = row >> 1;
    return (p << 7) + (((((row & 1) << 2) | ch) ^ (p & 7)) << 4);
}

#define CPA16(dst, src) \
    asm volatile("cp.async.cg.shared.global [%0], [%1], 16;" :: "r"(dst), "l"(src) : "memory")
#define CPA_COMMIT() asm volatile("cp.async.commit_group;" ::: "memory")
#define CPA_WAIT0()  asm volatile("cp.async.wait_group 0;"  ::: "memory")
#define CPA_WAIT1()  asm volatile("cp.async.wait_group 1;"  ::: "memory")

#define LDMX4(r0,r1,r2,r3, addr) \
    asm volatile("ldmatrix.sync.aligned.m8n8.x4.shared.b16 {%0,%1,%2,%3}, [%4];" \
        : "=r"(r0),"=r"(r1),"=r"(r2),"=r"(r3) : "r"(addr))

#define MMA16816(d, a, b0v, b1v) \
    asm volatile("mma.sync.aligned.m16n8k16.row.col.f32.bf16.bf16.f32 " \
        "{%0,%1,%2,%3}, {%4,%5,%6,%7}, {%8,%9}, {%0,%1,%2,%3};" \
        : "+f"((d)[0]),"+f"((d)[1]),"+f"((d)[2]),"+f"((d)[3]) \
        : "r"((a)[0]),"r"((a)[1]),"r"((a)[2]),"r"((a)[3]), "r"(b0v),"r"(b1v))

#define GEMM_SMEM (49152 + 1024)

// pack two fp32 values (cols col, col+1) into a 6-bf16 triple-A-mode run
__device__ __forceinline__ void store_triple2(__nv_bfloat16* p, float a, float b) {
    __nv_bfloat16 ha = __float2bfloat16(a);
    __nv_bfloat16 la = __float2bfloat16(a - __bfloat162float(ha));
    __nv_bfloat16 hb = __float2bfloat16(b);
    __nv_bfloat16 lb = __float2bfloat16(b - __bfloat162float(hb));
    uint32_t w0 = ((uint32_t)__bfloat16_as_ushort(ha) << 16) | __bfloat16_as_ushort(ha);
    uint32_t w1 = ((uint32_t)__bfloat16_as_ushort(hb) << 16) | __bfloat16_as_ushort(la);
    uint32_t w2 = ((uint32_t)__bfloat16_as_ushort(lb) << 16) | __bfloat16_as_ushort(hb);
    uint32_t* q = (uint32_t*)p;
    q[0] = w0; q[1] = w1; q[2] = w2;
}

// act: 0 plain fp32, 1 relu^2 fp32, 2 triple-bf16, 3 relu^2 + triple-bf16
__global__ void __launch_bounds__(256) hmma_gemm(
    const __nv_bfloat16* __restrict__ A, const __nv_bfloat16* __restrict__ B,
    const float* __restrict__ bias, float* __restrict__ C,
    int M, int N, int K3, int act)
{
    extern __shared__ char dsm_raw[];
    const uint32_t draw  = smem_u32(dsm_raw);
    const uint32_t dbase = (draw + 1023) & ~1023u;

    const int tid  = threadIdx.x;
    const int lane = tid & 31, wid = tid >> 5;

    // CTA rasterization swizzle: GM=8 M-tiles per launch-order group.
    const int nbn = gridDim.x;
    const int bid = blockIdx.y * nbn + blockIdx.x;
    const int grp = bid / (nbn << 3);
    const int rem = bid - grp * (nbn << 3);
    const int bm  = ((grp << 3) + (rem & 7)) << 7;
    const int bn  = (rem >> 3) << 7;

    const int wm = (wid >> 2) << 6;
    const int wn = (wid & 3) << 5;

    const int row0 = tid >> 2,         ch0 = tid & 3;
    const int row1 = (tid + 256) >> 2, ch1 = tid & 3;
    const int so0 = swoff(row0, ch0), so1 = swoff(row1, ch1);
    const __nv_bfloat16* Ag0 = A + (size_t)(bm + row0)*K3 + ch0*8;
    const __nv_bfloat16* Ag1 = A + (size_t)(bm + row1)*K3 + ch1*8;
    const __nv_bfloat16* Bg0 = B + (size_t)(bn + row0)*K3 + ch0*8;
    const __nv_bfloat16* Bg1 = B + (size_t)(bn + row1)*K3 + ch1*8;

    const int g = lane >> 3, rr = lane & 7;
    const int lrow_a = wm + ((g & 1) << 3) + rr;
    const int lrow_b = wn + ((g & 1) << 3) + rr;
    const int kc = g >> 1;

    float acc[4][4][4];
    #pragma unroll
    for (int i = 0; i < 4; i++)
        #pragma unroll
        for (int j = 0; j < 4; j++)
            #pragma unroll
            for (int r = 0; r < 4; r++) acc[i][j][r] = 0.f;

    const int nk = K3 >> 5;
    {
        const uint32_t sA = dbase, sB = dbase + 8192;
        CPA16(sA + so0, Ag0); CPA16(sA + so1, Ag1);
        CPA16(sB + so0, Bg0); CPA16(sB + so1, Bg1);
        CPA_COMMIT();
    }
    if (nk > 1) {
        const uint32_t sA = dbase + 16384, sB = dbase + 16384 + 8192;
        CPA16(sA + so0, Ag0 + 32); CPA16(sA + so1, Ag1 + 32);
        CPA16(sB + so0, Bg0 + 32); CPA16(sB + so1, Bg1 + 32);
        CPA_COMMIT();
        CPA_WAIT1();
    } else {
        CPA_WAIT0();
    }
    __syncthreads();

    for (int kt = 0; kt < nk; kt++) {
        const uint32_t buf = dbase + (kt % 3)*16384;
        const uint32_t bA = buf, bB = buf + 8192;
        #pragma unroll
        for (int ks = 0; ks < 2; ks++) {
            const int chunk = (ks << 1) + kc;
            uint32_t af[4][4];
            #pragma unroll
            for (int mi = 0; mi < 4; mi++) {
                uint32_t ad = bA + swoff(lrow_a + (mi << 4), chunk);
                LDMX4(af[mi][0], af[mi][1], af[mi][2], af[mi][3], ad);
            }
            uint32_t bf[4][2];
            #pragma unroll
            for (int bi = 0; bi < 2; bi++) {
                uint32_t t0, t1, t2, t3;
                uint32_t ad = bB + swoff(lrow_b + (bi << 4), chunk);
                LDMX4(t0, t1, t2, t3, ad);
                bf[bi*2  ][0] = t0; bf[bi*2+1][0] = t1;
                bf[bi*2  ][1] = t2; bf[bi*2+1][1] = t3;
            }
            #pragma unroll
            for (int mi = 0; mi < 4; mi++)
                #pragma unroll
                for (int nj = 0; nj < 4; nj++)
                    MMA16816(acc[mi][nj], af[mi], bf[nj][0], bf[nj][1]);
        }
        if (kt + 1 < nk) {
            if (kt + 2 < nk) {
                const int ko = (kt + 2) << 5;
                const uint32_t nb = dbase + ((kt + 2) % 3)*16384;
                CPA16(nb + so0,        Ag0 + ko); CPA16(nb + so1,        Ag1 + ko);
                CPA16(nb + 8192 + so0, Bg0 + ko); CPA16(nb + 8192 + so1, Bg1 + ko);
                CPA_COMMIT();
                CPA_WAIT1();
            } else {
                CPA_WAIT0();
            }
            __syncthreads();
        }
    }

    const int q  = lane >> 2;
    const int c2 = (lane & 3) << 1;
    #pragma unroll
    for (int mi = 0; mi < 4; mi++) {
        #pragma unroll
        for (int nj = 0; nj < 4; nj++) {
            const int col  = bn + wn + (nj << 3) + c2;
            const int row  = bm + wm + (mi << 4) + q;
            float b0v = bias[col], b1v = bias[col+1];
            float v0 = acc[mi][nj][0] + b0v;
            float v1 = acc[mi][nj][1] + b1v;
            float v2 = acc[mi][nj][2] + b0v;
            float v3 = acc[mi][nj][3] + b1v;
            if (act & 1) {
                v0 = fmaxf(v0, 0.f); v0 *= v0;
                v1 = fmaxf(v1, 0.f); v1 *= v1;
                v2 = fmaxf(v2, 0.f); v2 *= v2;
                v3 = fmaxf(v3, 0.f); v3 *= v3;
            }
            if (act < 2) {
                *(float2*)&C[(size_t)row*N + col]       = make_float2(v0, v1);
                *(float2*)&C[(size_t)(row + 8)*N + col] = make_float2(v2, v3);
            } else {
                __nv_bfloat16* Cb = (__nv_bfloat16*)C;
                store_triple2(Cb + (size_t)row*3*N       + 3*col, v0, v1);
                store_triple2(Cb + (size_t)(row + 8)*3*N + 3*col, v2, v3);
            }
        }
    }
}

// ---------------- 1) embedding gather + smear -> x_e3 (+ zero cnt/h0) --------
__global__ void __launch_bounds__(256) embed_kernel(
    const int* __restrict__ ids, const float* __restrict__ table,
    const float* __restrict__ smear_w, const float* __restrict__ smear_lambda)
{
    const int bt  = blockIdx.x;
    const int tid = threadIdx.x;
    if (tid == 0 && bt < NT)    g_cnt[bt] = 0;
    if (tid == 1 && bt < NB*NH) g_h[0][bt] = 0.f;

    const int t  = bt % NT;
    const int id = ids[bt];
    __shared__ float sgate;

    float v = 0.f;
    if (tid < 24) v = table[(size_t)id*NE + tid] * smear_w[tid];
    if (tid < 32) {
        #pragma unroll
        for (int off = 16; off; off >>= 1) v += __shfl_xor_sync(0xffffffffu, v, off);
        if (tid == 0) {
            float lam = smear_lambda[0];
            sgate = (t > 0) ? lam * (1.f/(1.f + __expf(-v))) : 0.f;
        }
    }
    __syncthreads();
    const float gate = sgate;
    const int idp = (t > 0) ? ids[bt-1] : 0;
    const float* rc = table + (size_t)id *NE;
    const float* rp = table + (size_t)idp*NE;
    __nv_bfloat16* dst = x_e3 + (size_t)bt*3*NE;
    for (int e = tid; e < NE; e += 256) {
        float x = rc[e] + gate*rp[e];
        __nv_bfloat16 h = __float2bfloat16(x);
        __nv_bfloat16 l = __float2bfloat16(x - __bfloat162float(h));
        dst[3*e] = h; dst[3*e+1] = h; dst[3*e+2] = l;
    }
}

// ---------------- persistent GRU scan: 16 warps (proven R13 sync) ------------
#define PACK2(out, lo, hi) \
    asm("mov.b64 %0, {%1, %2};" : "=l"(out) : "r"(__float_as_uint(lo)), "r"(__float_as_uint(hi)))
#define UNPACK2(lo, hi, in) do { uint32_t _a, _b; \
    asm("mov.b64 {%0, %1}, %2;" : "=r"(_a), "=r"(_b) : "l"(in)); \
    lo = __uint_as_float(_a); hi = __uint_as_float(_b); } while(0)
#define FMA2(acc, a, b) \
    asm("fma.rn.f32x2 %0, %1, %2, %0;" : "+l"(acc) : "l"(a), "l"(b))

__global__ void __launch_bounds__(512) gru_kernel(
    const float* __restrict__ w_hh, const float* __restrict__ b_hh)
{
    __shared__ __align__(16) float sh[2*NH];
    const int tid  = threadIdx.x;
    const int lane = tid & 31, w = tid >> 5;
    const int jj   = w >> 1, bb = w & 1;
    const int j    = (blockIdx.x << 3) + jj;

    unsigned long long wpk[3][16];
    #pragma unroll
    for (int g2 = 0; g2 < 3; g2++) {
        const float4* src = (const float4*)(w_hh + ((size_t)g2*NH + j)*NH);
        #pragma unroll
        for (int i = 0; i < 8; i++) {
            float4 v = src[i*32 + lane];
            PACK2(wpk[g2][2*i],   v.x, v.y);
            PACK2(wpk[g2][2*i+1], v.z, v.w);
        }
    }
    float bh_r = 0.f, bh_z = 0.f, bh_n = 0.f;
    if (lane == 0) { bh_r = b_hh[j]; bh_z = b_hh[NH + j]; bh_n = b_hh[2*NH + j]; }

    const ulonglong2* sbb = (const ulonglong2*)(sh + bb*NH);

    for (int t = 0; t < NT; t++) {
        float xv = 0.f;
        if (lane < 3)
            xv = g_xproj[((size_t)(bb*NT + t))*(3*NH) + lane*NH + j];

        if (t > 0) {
            if (tid < 32) {
                const int* cp = g_cnt + (t-1);
                int v;
                do {
                    asm volatile("ld.relaxed.gpu.global.s32 %0, [%1];"
                                 : "=r"(v) : "l"(cp) : "memory");
                } while (v < GRU_CTAS);
                asm volatile("ld.acquire.gpu.global.s32 %0, [%1];"
                             : "=r"(v) : "l"(cp) : "memory");
            }
            __syncthreads();
        }
        {
            float4 hv = __ldcg((const float4*)g_h[t & 1] + tid);
            ((float4*)sh)[tid] = hv;
        }
        __syncthreads();

        unsigned long long a_r = 0ull, a_z = 0ull, a_n = 0ull;
        #pragma unroll
        for (int ii = 0; ii < 8; ii++) {
            ulonglong2 h2 = sbb[ii*32 + lane];
            FMA2(a_r, wpk[0][2*ii], h2.x); FMA2(a_r, wpk[0][2*ii+1], h2.y);
            FMA2(a_z, wpk[1][2*ii], h2.x); FMA2(a_z, wpk[1][2*ii+1], h2.y);
            FMA2(a_n, wpk[2][2*ii], h2.x); FMA2(a_n, wpk[2][2*ii+1], h2.y);
        }
        float t0, t1;
        UNPACK2(t0, t1, a_r); float sr = t0 + t1;
        UNPACK2(t0, t1, a_z); float sz = t0 + t1;
        UNPACK2(t0, t1, a_n); float sn = t0 + t1;
        #pragma unroll
        for (int off = 16; off; off >>= 1) {
            sr += __shfl_xor_sync(0xffffffffu, sr, off);
            sz += __shfl_xor_sync(0xffffffffu, sz, off);
            sn += __shfl_xor_sync(0xffffffffu, sn, off);
        }
        float xr = __shfl_sync(0xffffffffu, xv, 0);
        float xz = __shfl_sync(0xffffffffu, xv, 1);
        float xn = __shfl_sync(0xffffffffu, xv, 2);
        float hnew = 0.f;
        if (lane == 0) {
            float rr = 1.f/(1.f + __expf(-(xr + sr + bh_r)));
            float zz = 1.f/(1.f + __expf(-(xz + sz + bh_z)));
            float nn = tanhf(xn + rr*(sn + bh_n));
            float hold = sh[bb*NH + j];
            hnew = (1.f - zz)*nn + zz*hold;
            __stcg(&g_h[(t+1) & 1][bb*NH + j], hnew);
        }
        __syncthreads();
        if (tid == 0) {
            asm volatile("red.release.gpu.global.add.s32 [%0], %1;"
                         :: "l"(g_cnt + t), "r"(1) : "memory");
        }
        if (lane == 0) {
            g_states[((size_t)(bb*NT + t))*NH + j] = hnew;
            __nv_bfloat16 hh = __float2bfloat16(hnew);
            __nv_bfloat16 hl = __float2bfloat16(hnew - __bfloat162float(hh));
            __nv_bfloat16* s3 = x_s3 + ((size_t)(bb*NT + t))*(3*NH) + 3*j;
            s3[0] = hh; s3[1] = hh; s3[2] = hl;
        }
    }
}

// ---------------- bias concat for fused q/k GEMM ------------------------------
__global__ void concat_bias(const float* __restrict__ bq, const float* __restrict__ bk)
{
    int i = threadIdx.x;
    g_bqk[i] = (i < NM) ? bq[i] : bk[i - NM];
}

// ---------------- g = sigmoid(states @ wg^T + bg) ----------------------------
__global__ void __launch_bounds__(256) g_kernel(
    const float* __restrict__ wg, const float* __restrict__ bg)
{
    const int row  = (blockIdx.x << 3) + (threadIdx.x >> 5);
    const int lane = threadIdx.x & 31;
    const float* s = g_states + (size_t)row*NH;
    float acc = 0.f;
    #pragma unroll 8
    for (int i = 0; i < 32; i++) acc += s[lane + (i<<5)] * wg[lane + (i<<5)];
    #pragma unroll
    for (int off = 16; off; off >>= 1) acc += __shfl_xor_sync(0xffffffffu, acc, off);
    if (lane == 0) g_gate[row] = 1.f/(1.f + __expf(-(acc + bg[0])));
}

// ---------------- causal attention + fused vocab scatter ---------------------
__global__ void __launch_bounds__(256) attn_kernel(
    const int* __restrict__ ids, float* __restrict__ out,
    const float* __restrict__ mscale_p)
{
    const int t = blockIdx.x;
    const int b = blockIdx.y;
    if (t == 0) return;

    __shared__ float sc[NT];
    __shared__ __align__(16) float qs[NM];
    __shared__ float red[8];
    const int tid = threadIdx.x;
    const int lane = tid & 31, wp = tid >> 5;

    if (tid < NM) qs[tid] = g_qk[((size_t)(b*NT + t))*(2*NM) + tid];
    __syncthreads();
    const float4* q4 = (const float4*)qs;

    float lmax = -1e30f;
    for (int s = tid; s < t; s += 256) {
        const float4* k4 = (const float4*)(g_qk + ((size_t)(b*NT + s))*(2*NM) + NM);
        float acc = 0.f;
        #pragma unroll
        for (int c = 0; c < 32; c++) {
            float4 qv = q4[c]; float4 kv = k4[c];
            acc += qv.x*kv.x + qv.y*kv.y + qv.z*kv.z + qv.w*kv.w;
        }
        acc *= 0.0883883476483184f;
        sc[s] = acc;
        lmax = fmaxf(lmax, acc);
    }
    #pragma unroll
    for (int off = 16; off; off >>= 1) lmax = fmaxf(lmax, __shfl_xor_sync(0xffffffffu, lmax, off));
    if (lane == 0) red[wp] = lmax;
    __syncthreads();
    if (tid == 0) {
        float m = red[0];
        #pragma unroll
        for (int i = 1; i < 8; i++) m = fmaxf(m, red[i]);
        red[0] = m;
    }
    __syncthreads();
    const float smax = red[0];
    __syncthreads();

    float lsum = 0.f;
    for (int s = tid; s < t; s += 256) {
        float e = __expf(sc[s] - smax);
        sc[s] = e;
        lsum += e;
    }
    #pragma unroll
    for (int off = 16; off; off >>= 1) lsum += __shfl_xor_sync(0xffffffffu, lsum, off);
    if (lane == 0) red[wp] = lsum;
    __syncthreads();
    if (tid == 0) {
        float ssum = 0.f;
        #pragma unroll
        for (int i = 0; i < 8; i++) ssum += red[i];
        red[0] = ssum;
    }
    __syncthreads();
    const float ssum = fmaxf(red[0], 1e-6f);
    const float scale = g_gate[b*NT + t] * mscale_p[0] / ssum;

    float* orow = out + ((size_t)(b*NT + t))*NV;
    const int* idr = ids + b*NT;
    for (int s = tid; s < t; s += 256)
        atomicAdd(&orow[idr[s]], sc[s]*scale);
}

// ---------------- launcher ----------------------------------------------------
extern "C" void kernel_launch(void* const* d_in, const int* in_sizes, int n_in,
                              void* d_out, int out_size)
{
    const int*   ids     = (const int*)  d_in[0];
    const float* table   = (const float*)d_in[1];
    const float* w_ih    = (const float*)d_in[2];
    const float* w_hh    = (const float*)d_in[3];
    const float* b_ih    = (const float*)d_in[4];
    const float* b_hh    = (const float*)d_in[5];
    const float* wq      = (const float*)d_in[6];
    const float* bq      = (const float*)d_in[7];
    const float* wk      = (const float*)d_in[8];
    const float* bk      = (const float*)d_in[9];
    const float* wg      = (const float*)d_in[10];
    const float* bg      = (const float*)d_in[11];
    const float* w_fc    = (const float*)d_in[12];
    const float* b_fc    = (const float*)d_in[13];
    const float* w_proj  = (const float*)d_in[14];
    const float* b_proj  = (const float*)d_in[15];
    const float* out_b   = (const float*)d_in[16];
    const float* mscale  = (const float*)d_in[17];
    const float* smear_w = (const float*)d_in[18];
    const float* smear_l = (const float*)d_in[19];
    float* out = (float*)d_out;
    (void)in_sizes; (void)n_in; (void)out_size;

    void *p_xproj, *p_states, *p_qk, *p_bqkv;
    void *p_e3, *p_wih3, *p_s3, *p_wfc3, *p_hd3, *p_wp3, *p_f3, *p_t3, *p_wqk3;
    cudaGetSymbolAddress(&p_xproj,  g_xproj);
    cudaGetSymbolAddress(&p_states, g_states);
    cudaGetSymbolAddress(&p_qk,     g_qk);
    cudaGetSymbolAddress(&p_bqkv,   g_bqk);
    cudaGetSymbolAddress(&p_e3,     x_e3);
    cudaGetSymbolAddress(&p_wih3,   x_wih3);
    cudaGetSymbolAddress(&p_s3,     x_s3);
    cudaGetSymbolAddress(&p_wfc3,   x_wfc3);
    cudaGetSymbolAddress(&p_hd3,    x_hd3);
    cudaGetSymbolAddress(&p_wp3,    x_wp3);
    cudaGetSymbolAddress(&p_f3,     x_f3);
    cudaGetSymbolAddress(&p_t3,     x_t3);
    cudaGetSymbolAddress(&p_wqk3,   x_wqk3);

    cudaFuncSetAttribute(hmma_gemm, cudaFuncAttributeMaxDynamicSharedMemorySize, GEMM_SMEM);

    // persistent side stream + fork/join events (created once; capture-safe)
    static cudaStream_t s2 = (cudaStream_t)nullptr;
    static cudaEvent_t evFork = (cudaEvent_t)nullptr, evJoin = (cudaEvent_t)nullptr;
    if (s2 == nullptr) {
        cudaStreamCreateWithFlags(&s2, cudaStreamNonBlocking);
        cudaEventCreateWithFlags(&evFork, cudaEventDisableTiming);
        cudaEventCreateWithFlags(&evJoin, cudaEventDisableTiming);
    }

    #define EXPAND_ON(st, srcp, dstp, nelem, mode) \
        expand3_kernel<<<((nelem)/8 + 255)/256, 256, 0, st>>>((const float*)(srcp), (__nv_bfloat16*)(dstp), (nelem)/8, mode)

    // 1) embedding + smear -> x_e3 (+ zero barrier counters and h0)
    embed_kernel<<<NROW, 256>>>(ids, table, smear_w, smear_l);

    // fork: GRU-independent prep overlaps with xproj GEMM + GRU scan
    cudaEventRecord(evFork, 0);
    cudaStreamWaitEvent(s2, evFork, 0);
    EXPAND_ON(s2, w_fc,   p_wfc3, 4*NE*NH, 1);
    EXPAND_ON(s2, w_proj, p_wp3,  NE*4*NE, 1);
    EXPAND_ON(s2, table,  p_t3,   NV*NE,   1);
    EXPAND_ON(s2, wq,     p_wqk3, NM*NH,   1);
    expand3_kernel<<<(NM*NH/8 + 255)/256, 256, 0, s2>>>(
        wk, (__nv_bfloat16*)p_wqk3 + (size_t)NM*3*NH, NM*NH/8, 1);
    concat_bias<<<1, 2*NM, 0, s2>>>(bq, bk);
    cudaEventRecord(evJoin, s2);

    // 2) x_proj = emb @ w_ih^T + b_ih        [4096,3072], K3=1536
    EXPAND_ON(0, w_ih, p_wih3, 3*NH*NE, 1);
    hmma_gemm<<<dim3(24,32), 256, GEMM_SMEM>>>((const __nv_bfloat16*)p_e3, (const __nv_bfloat16*)p_wih3,
                                               b_ih, (float*)p_xproj, NROW, 3*NH, 3*NE, 0);
    // 3) GRU scan -> g_states + x_s3
    gru_kernel<<<GRU_CTAS, 512>>>(w_hh, b_hh);

    // join: prep must be done before head GEMM consumes wfc3
    cudaStreamWaitEvent(0, evJoin, 0);

    // 4) head = relu^2(states @ w_fc^T + b_fc) -> x_hd3 DIRECT (act=3)
    hmma_gemm<<<dim3(16,32), 256, GEMM_SMEM>>>((const __nv_bfloat16*)p_s3, (const __nv_bfloat16*)p_wfc3,
                                               b_fc, (float*)p_hd3, NROW, 4*NE, 3*NH, 3);
    // 5) base_feat = head @ w_proj^T + b_proj -> x_f3 DIRECT (act=2)
    hmma_gemm<<<dim3(4,32), 256, GEMM_SMEM>>>((const __nv_bfloat16*)p_hd3, (const __nv_bfloat16*)p_wp3,
                                              b_proj, (float*)p_f3, NROW, NE, 3*4*NE, 2);
    // 6) logits = base_feat @ emb_table^T + out_b -> d_out [4096,32000], K3=1536
    hmma_gemm<<<dim3(250,32), 256, GEMM_SMEM>>>((const __nv_bfloat16*)p_f3, (const __nv_bfloat16*)p_t3,
                                                out_b, out, NROW, NV, 3*NE, 0);
    // 7) fused q/k GEMM: [4096, 256], K3=3072
    hmma_gemm<<<dim3(2,32), 256, GEMM_SMEM>>>((const __nv_bfloat16*)p_s3, (const __nv_bfloat16*)p_wqk3,
                                              (const float*)p_bqkv, (float*)p_qk, NROW, 2*NM, 3*NH, 0);
    // 8) g = sigmoid(states @ wg^T + bg)
    g_kernel<<<NROW/8, 256>>>(wg, bg);
    // 9) causal attention + scatter-add into d_out
    attn_kernel<<<dim3(NT, NB), 256>>>(ids, out, mscale);
    #undef EXPAND_ON
}